// round 13
// baseline (speedup 1.0000x reference)
#include <cuda_runtime.h>
#include <cstdint>

// Problem constants
#define T_SEQ 200
#define BATCH 1024
#define EMB   128
#define HID   128
#define G3    384          // 3*HID, gate order r,z,n
#define NROWS (BATCH * T_SEQ)
#define VOCAB 100000

// 314 MB scratch for gx = x @ W_ih^T + b_ih  (static __device__: allocation-free)
__device__ float g_gx[(size_t)NROWS * G3];

// Precomputed bf16 hi/lo splits (written once per launch by split kernels)
__device__ unsigned short g_embh[(size_t)VOCAB * EMB];
__device__ unsigned short g_embl[(size_t)VOCAB * EMB];
__device__ unsigned short g_wihh[G3 * EMB];
__device__ unsigned short g_wihl[G3 * EMB];

// ---- bf16 split helpers (RNE via bit trick, matches cvt.rn.bf16) ----
__device__ __forceinline__ unsigned bf16bits(float x) {      // top-16 bits, rounded
    unsigned u = __float_as_uint(x);
    return ((u + 0x7fffu + ((u >> 16) & 1u)) & 0xffff0000u);
}
__device__ __forceinline__ void bsplit(float x, unsigned& h16, unsigned& l16) {
    unsigned uh = bf16bits(x);
    float hi = __uint_as_float(uh);
    float lo = x - hi;
    h16 = uh >> 16;
    l16 = bf16bits(lo) >> 16;
}

// D += A*B  (m16n8k16 bf16, fp32 accum)
__device__ __forceinline__ void mma_bf16(float* c,
                                         unsigned a0, unsigned a1, unsigned a2, unsigned a3,
                                         unsigned b0, unsigned b1) {
    asm("mma.sync.aligned.m16n8k16.row.col.f32.bf16.bf16.f32 "
        "{%0,%1,%2,%3}, {%4,%5,%6,%7}, {%8,%9}, {%0,%1,%2,%3};"
        : "+f"(c[0]), "+f"(c[1]), "+f"(c[2]), "+f"(c[3])
        : "r"(a0), "r"(a1), "r"(a2), "r"(a3), "r"(b0), "r"(b1));
}

// ---------------------------------------------------------------------------
// Kernel 0: split a float array into bf16 hi/lo tables (DRAM-bound, ~20 us)
// ---------------------------------------------------------------------------
__global__ __launch_bounds__(256) void split_kernel(
    const float* __restrict__ src,
    unsigned short* __restrict__ dh,
    unsigned short* __restrict__ dl,
    int n4)
{
    int idx = blockIdx.x * blockDim.x + threadIdx.x;
    if (idx >= n4) return;
    float4 v = ((const float4*)src)[idx];
    unsigned h0,l0,h1,l1,h2,l2,h3,l3;
    bsplit(v.x,h0,l0); bsplit(v.y,h1,l1);
    bsplit(v.z,h2,l2); bsplit(v.w,h3,l3);
    ((uint2*)dh)[idx] = make_uint2(h0 | (h1 << 16), h2 | (h3 << 16));
    ((uint2*)dl)[idx] = make_uint2(l0 | (l1 << 16), l2 | (l3 << 16));
}

// ---------------------------------------------------------------------------
// Kernel 1: fused embedding gather + input GEMM on tensor cores (bf16 3-pass).
// MT=128 (reverted — R12's MT=64 regressed). Staging = pure gather-copy.
// ---------------------------------------------------------------------------
#define MT    128
#define PITCH 136
#define SM1_BYTES (4 * 128 * PITCH * 2)

__global__ __launch_bounds__(256) void gx_kernel(
    const int*   __restrict__ seq,
    const float* __restrict__ bih)
{
    extern __shared__ unsigned short smu[];
    unsigned short* xh = smu;                    // [128][PITCH] bf16
    unsigned short* xl = xh + 128 * PITCH;
    unsigned short* wh = xl + 128 * PITCH;
    unsigned short* wl = wh + 128 * PITCH;

    const int t    = threadIdx.x;
    const int row0 = blockIdx.x * MT;
    const int c0   = blockIdx.y * 128;

    {
        int r  = t >> 1;
        int k0 = (t & 1) * 64;
        int idx = __ldg(seq + row0 + r);
        const uint4* sh = (const uint4*)(g_embh + (size_t)idx * EMB + k0);
        const uint4* sl = (const uint4*)(g_embl + (size_t)idx * EMB + k0);
        int o = r * PITCH + k0;
        #pragma unroll
        for (int i = 0; i < 8; i++) {
            *(uint4*)(xh + o + 8 * i) = sh[i];
            *(uint4*)(xl + o + 8 * i) = sl[i];
        }
    }
    {
        int c  = t >> 1;
        int k0 = (t & 1) * 64;
        const uint4* sh = (const uint4*)(g_wihh + (size_t)(c0 + c) * EMB + k0);
        const uint4* sl = (const uint4*)(g_wihl + (size_t)(c0 + c) * EMB + k0);
        int o = c * PITCH + k0;
        #pragma unroll
        for (int i = 0; i < 8; i++) {
            *(uint4*)(wh + o + 8 * i) = sh[i];
            *(uint4*)(wl + o + 8 * i) = sl[i];
        }
    }
    __syncthreads();

    const int w     = t >> 5;
    const int lane  = t & 31;
    const int mrow0 = (w & 3) * 32;
    const int ncol0 = (w >> 2) * 64;
    const int g     = lane >> 2;       // 0..7
    const int tg    = lane & 3;        // 0..3

    float acc[2][8][4];
    #pragma unroll
    for (int m = 0; m < 2; m++)
        #pragma unroll
        for (int n = 0; n < 8; n++)
            #pragma unroll
            for (int i = 0; i < 4; i++) acc[m][n][i] = 0.f;

    #pragma unroll
    for (int kt = 0; kt < 8; kt++) {
        const int k0 = kt * 16;
        unsigned ah[2][4], al[2][4];
        #pragma unroll
        for (int m = 0; m < 2; m++) {
            const unsigned short* p = xh + (mrow0 + 16 * m + g) * PITCH + k0 + 2 * tg;
            const unsigned short* q = xl + (mrow0 + 16 * m + g) * PITCH + k0 + 2 * tg;
            ah[m][0] = *(const unsigned*)(p);
            ah[m][1] = *(const unsigned*)(p + 8 * PITCH);
            ah[m][2] = *(const unsigned*)(p + 8);
            ah[m][3] = *(const unsigned*)(p + 8 * PITCH + 8);
            al[m][0] = *(const unsigned*)(q);
            al[m][1] = *(const unsigned*)(q + 8 * PITCH);
            al[m][2] = *(const unsigned*)(q + 8);
            al[m][3] = *(const unsigned*)(q + 8 * PITCH + 8);
        }
        #pragma unroll
        for (int n = 0; n < 8; n++) {
            const unsigned short* p = wh + (ncol0 + 8 * n + g) * PITCH + k0 + 2 * tg;
            const unsigned short* q = wl + (ncol0 + 8 * n + g) * PITCH + k0 + 2 * tg;
            unsigned bh0 = *(const unsigned*)(p);
            unsigned bh1 = *(const unsigned*)(p + 8);
            unsigned bl0 = *(const unsigned*)(q);
            unsigned bl1 = *(const unsigned*)(q + 8);
            #pragma unroll
            for (int m = 0; m < 2; m++) {
                mma_bf16(acc[m][n], ah[m][0], ah[m][1], ah[m][2], ah[m][3], bh0, bh1);
                mma_bf16(acc[m][n], ah[m][0], ah[m][1], ah[m][2], ah[m][3], bl0, bl1);
                mma_bf16(acc[m][n], al[m][0], al[m][1], al[m][2], al[m][3], bh0, bh1);
            }
        }
    }

    #pragma unroll
    for (int n = 0; n < 8; n++) {
        int col = c0 + ncol0 + n * 8 + 2 * tg;
        float2 bv = *(const float2*)(bih + col);
        #pragma unroll
        for (int m = 0; m < 2; m++) {
            int r0 = row0 + mrow0 + m * 16 + g;
            float2 v0 = { acc[m][n][0] + bv.x, acc[m][n][1] + bv.y };
            float2 v1 = { acc[m][n][2] + bv.x, acc[m][n][3] + bv.y };
            *(float2*)(g_gx + (size_t)r0 * G3 + col)       = v0;
            *(float2*)(g_gx + (size_t)(r0 + 8) * G3 + col) = v1;
        }
    }
}

// ---------------------------------------------------------------------------
// Kernel 2: GRU recurrence on tensor cores, register-resident gate fusion.
// Warp w owns n-tiles {16w, 16w+8} in EACH gate group (r/z/n) so its own
// D-fragment holds the full r/z/n triplet for its phase-2 lanes: gate math
// runs directly on mma accumulators (no ghs SMEM stage, no 2nd barrier).
// h double-buffered as packed bf16 hi/lo words -> 1 barrier/step.
// 2-pass mma: lo-split in A rows 8-15; gh = c0+c2 (exact (hi+lo)*(whi+wlo)).
// ---------------------------------------------------------------------------
#define BM     8
#define HPITCH 68
#define HBUF   (BM * HPITCH)
#define SM2_BYTES ((49152 + 4 * HBUF) * 4)

__device__ __forceinline__ float fsigmoid(float x) {
    return __fdividef(1.f, 1.f + __expf(-x));
}

__global__ __launch_bounds__(256) void gru_kernel(
    const float* __restrict__ Whh,
    const float* __restrict__ bhh,
    float*       __restrict__ out)
{
    extern __shared__ float sm[];
    uint2*    wfrag = (uint2*)sm;                  // [8w][6i][8j][2s][32l]
    unsigned* hbase = (unsigned*)(sm + 49152);     // 2 x (hhi[HBUF], hlo[HBUF])

    const int t  = threadIdx.x;
    const int w  = t >> 5;
    const int l  = t & 31;
    const int g  = l >> 2;        // batch row owned in phase 2 (D row)
    const int tg = l & 3;
    const int b0 = blockIdx.x * BM;

    // ---- precompute W_hh fragments; gate mapping: i -> group (i>>1), subtile (i&1)
    #pragma unroll
    for (int i = 0; i < 6; i++) {
        #pragma unroll
        for (int j = 0; j < 8; j++) {
            int n  = (i >> 1) * 128 + 16 * w + 8 * (i & 1) + g;
            int kb = 16 * j + 2 * tg;
            const float* Wr = Whh + (size_t)n * HID;
            float w00 = Wr[kb],     w01 = Wr[kb + 1];
            float w08 = Wr[kb + 8], w09 = Wr[kb + 9];
            unsigned h00, l00, h01, l01, h08, l08, h09, l09;
            bsplit(w00, h00, l00);  bsplit(w01, h01, l01);
            bsplit(w08, h08, l08);  bsplit(w09, h09, l09);
            int base = ((w * 6 + i) * 8 + j) * 2;
            wfrag[(base + 0) * 32 + l] = make_uint2(h00 | (h01 << 16), h08 | (h09 << 16));
            wfrag[(base + 1) * 32 + l] = make_uint2(l00 | (l01 << 16), l08 | (l09 << 16));
        }
    }
    for (int p = t; p < 4 * HBUF; p += 256) hbase[p] = 0u;

    // bias for this thread's 6 gate pairs
    float2 bias[6];
    #pragma unroll
    for (int i = 0; i < 6; i++)
        bias[i] = *(const float2*)(bhh + (i >> 1) * 128 + 16 * w + 8 * (i & 1) + 2 * tg);

    // phase-2 register-resident h: row g, k in {ka, ka+1, kb2, kb2+1}
    const int ka  = 16 * w + 2 * tg;
    const int kb2 = ka + 8;
    float h0 = 0.f, h1 = 0.f, h2 = 0.f, h3 = 0.f;
    const int row = b0 + g;
    const size_t gxbase = (size_t)row * T_SEQ * G3;

    const uint2* pw = wfrag + (w * 96) * 32 + l;
    __syncthreads();

    int cur = 0;
    for (int ts = 0; ts < T_SEQ; ts++) {
        unsigned* hhi_c = hbase + cur * 2 * HBUF;
        unsigned* hlo_c = hhi_c + HBUF;
        unsigned* hhi_n = hbase + (cur ^ 1) * 2 * HBUF;
        unsigned* hlo_n = hhi_n + HBUF;

        // ---- prefetch this thread's gx (row g, its own 4 k positions)
        const float* gp = g_gx + gxbase + (size_t)ts * G3;
        float2 xra = __ldg((const float2*)(gp + ka));
        float2 xrb = __ldg((const float2*)(gp + kb2));
        float2 xza = __ldg((const float2*)(gp + 128 + ka));
        float2 xzb = __ldg((const float2*)(gp + 128 + kb2));
        float2 xna = __ldg((const float2*)(gp + 256 + ka));
        float2 xnb = __ldg((const float2*)(gp + 256 + kb2));

        // ---- mma: gh = h @ W_hh^T (2-pass, hi|lo packed in A rows 0-7|8-15)
        float acc[6][4];
        #pragma unroll
        for (int i = 0; i < 6; i++)
            { acc[i][0]=0.f; acc[i][1]=0.f; acc[i][2]=0.f; acc[i][3]=0.f; }

        #pragma unroll
        for (int j = 0; j < 8; j++) {
            unsigned ahi0 = hhi_c[g * HPITCH + 8 * j + tg];
            unsigned ahi2 = hhi_c[g * HPITCH + 8 * j + tg + 4];
            unsigned alo0 = hlo_c[g * HPITCH + 8 * j + tg];
            unsigned alo2 = hlo_c[g * HPITCH + 8 * j + tg + 4];
            #pragma unroll
            for (int i = 0; i < 6; i++) {
                uint2 bh = pw[((i * 8 + j) * 2 + 0) * 32];
                uint2 bl = pw[((i * 8 + j) * 2 + 1) * 32];
                mma_bf16(acc[i], ahi0, alo0, ahi2, alo2, bh.x, bh.y);
                mma_bf16(acc[i], ahi0, alo0, ahi2, alo2, bl.x, bl.y);
            }
        }

        // ---- gate math directly on accumulators (row g, 4 k positions)
        float gr0 = acc[0][0] + acc[0][2] + bias[0].x;
        float gr1 = acc[0][1] + acc[0][3] + bias[0].y;
        float gr2 = acc[1][0] + acc[1][2] + bias[1].x;
        float gr3 = acc[1][1] + acc[1][3] + bias[1].y;
        float gz0 = acc[2][0] + acc[2][2] + bias[2].x;
        float gz1 = acc[2][1] + acc[2][3] + bias[2].y;
        float gz2 = acc[3][0] + acc[3][2] + bias[3].x;
        float gz3 = acc[3][1] + acc[3][3] + bias[3].y;
        float gn0 = acc[4][0] + acc[4][2] + bias[4].x;
        float gn1 = acc[4][1] + acc[4][3] + bias[4].y;
        float gn2 = acc[5][0] + acc[5][2] + bias[5].x;
        float gn3 = acc[5][1] + acc[5][3] + bias[5].y;

        float r0 = fsigmoid(xra.x + gr0), r1 = fsigmoid(xra.y + gr1);
        float r2 = fsigmoid(xrb.x + gr2), r3 = fsigmoid(xrb.y + gr3);
        float z0 = fsigmoid(xza.x + gz0), z1 = fsigmoid(xza.y + gz1);
        float z2 = fsigmoid(xzb.x + gz2), z3 = fsigmoid(xzb.y + gz3);
        float n0 = 2.f * fsigmoid(2.f * (xna.x + r0 * gn0)) - 1.f;
        float n1 = 2.f * fsigmoid(2.f * (xna.y + r1 * gn1)) - 1.f;
        float n2 = 2.f * fsigmoid(2.f * (xnb.x + r2 * gn2)) - 1.f;
        float n3 = 2.f * fsigmoid(2.f * (xnb.y + r3 * gn3)) - 1.f;

        h0 = (1.f - z0) * n0 + z0 * h0;
        h1 = (1.f - z1) * n1 + z1 * h1;
        h2 = (1.f - z2) * n2 + z2 * h2;
        h3 = (1.f - z3) * n3 + z3 * h3;

        // ---- write next-step A operands (packed bf16 hi/lo), double-buffered
        {
            unsigned ha0, la0, ha1, la1;
            bsplit(h0, ha0, la0);  bsplit(h1, ha1, la1);
            hhi_n[g * HPITCH + 8 * w + tg] = ha0 | (ha1 << 16);
            hlo_n[g * HPITCH + 8 * w + tg] = la0 | (la1 << 16);
            bsplit(h2, ha0, la0);  bsplit(h3, ha1, la1);
            hhi_n[g * HPITCH + 8 * w + tg + 4] = ha0 | (ha1 << 16);
            hlo_n[g * HPITCH + 8 * w + tg + 4] = la0 | (la1 << 16);
        }
        __syncthreads();
        cur ^= 1;
    }

    // ---- final hidden state straight from registers
    {
        float2 va = { h0, h1 };
        float2 vb = { h2, h3 };
        *(float2*)(out + (size_t)row * HID + ka)  = va;
        *(float2*)(out + (size_t)row * HID + kb2) = vb;
    }
}

// ---------------------------------------------------------------------------
// Launch
// ---------------------------------------------------------------------------
extern "C" void kernel_launch(void* const* d_in, const int* in_sizes, int n_in,
                              void* d_out, int out_size)
{
    const int*   seq = (const int*)  d_in[0];  // [1024, 200] int32
    const float* emb = (const float*)d_in[1];  // [100000, 128]
    const float* Wih = (const float*)d_in[2];  // [384, 128]
    const float* Whh = (const float*)d_in[3];  // [384, 128]
    const float* bih = (const float*)d_in[4];  // [384]
    const float* bhh = (const float*)d_in[5];  // [384]
    float* out = (float*)d_out;                // [1024, 128]

    cudaFuncSetAttribute(gx_kernel,  cudaFuncAttributeMaxDynamicSharedMemorySize, SM1_BYTES);
    cudaFuncSetAttribute(gru_kernel, cudaFuncAttributeMaxDynamicSharedMemorySize, SM2_BYTES);

    unsigned short *p_embh, *p_embl, *p_wihh, *p_wihl;
    cudaGetSymbolAddress((void**)&p_embh, g_embh);
    cudaGetSymbolAddress((void**)&p_embl, g_embl);
    cudaGetSymbolAddress((void**)&p_wihh, g_wihh);
    cudaGetSymbolAddress((void**)&p_wihl, g_wihl);

    int n4e = VOCAB * EMB / 4;                 // 3.2M float4s
    split_kernel<<<(n4e + 255) / 256, 256>>>(emb, p_embh, p_embl, n4e);
    int n4w = G3 * EMB / 4;                    // 12288 float4s
    split_kernel<<<(n4w + 255) / 256, 256>>>(Wih, p_wihh, p_wihl, n4w);

    dim3 grid1(NROWS / MT, G3 / 128);          // 1600 x 3
    gx_kernel<<<grid1, 256, SM1_BYTES>>>(seq, bih);

    gru_kernel<<<BATCH / BM, 256, SM2_BYTES>>>(Whh, bhh, out);
}

// round 14
// speedup vs baseline: 1.1590x; 1.1590x over previous
#include <cuda_runtime.h>
#include <cstdint>

// Problem constants
#define T_SEQ 200
#define BATCH 1024
#define EMB   128
#define HID   128
#define G3    384          // 3*HID, gate order r,z,n
#define NROWS (BATCH * T_SEQ)

// 314 MB scratch for gx = x @ W_ih^T + b_ih  (static __device__: allocation-free)
__device__ float g_gx[(size_t)NROWS * G3];

// ---- bf16 split helpers (RNE via bit trick, matches cvt.rn.bf16) ----
__device__ __forceinline__ unsigned bf16bits(float x) {      // top-16 bits, rounded
    unsigned u = __float_as_uint(x);
    return ((u + 0x7fffu + ((u >> 16) & 1u)) & 0xffff0000u);
}
__device__ __forceinline__ void bsplit(float x, unsigned& h16, unsigned& l16) {
    unsigned uh = bf16bits(x);
    float hi = __uint_as_float(uh);
    float lo = x - hi;
    h16 = uh >> 16;
    l16 = bf16bits(lo) >> 16;
}

// D += A*B  (m16n8k16 bf16, fp32 accum)
__device__ __forceinline__ void mma_bf16(float* c,
                                         unsigned a0, unsigned a1, unsigned a2, unsigned a3,
                                         unsigned b0, unsigned b1) {
    asm("mma.sync.aligned.m16n8k16.row.col.f32.bf16.bf16.f32 "
        "{%0,%1,%2,%3}, {%4,%5,%6,%7}, {%8,%9}, {%0,%1,%2,%3};"
        : "+f"(c[0]), "+f"(c[1]), "+f"(c[2]), "+f"(c[3])
        : "r"(a0), "r"(a1), "r"(a2), "r"(a3), "r"(b0), "r"(b1));
}

// ---------------------------------------------------------------------------
// Kernel 1: fused embedding gather + input GEMM on tensor cores (bf16 3-pass).
// R8 version verbatim (best measured: ~401 us incl. overlap): inline hi/lo
// split at staging, MT=128, pure 32-bit LDS + HMMA hot loop.
// ---------------------------------------------------------------------------
#define MT    128
#define PITCH 136
#define SM1_BYTES (4 * 128 * PITCH * 2)

__global__ __launch_bounds__(256) void gx_kernel(
    const int*   __restrict__ seq,
    const float* __restrict__ emb,
    const float* __restrict__ Wih,
    const float* __restrict__ bih)
{
    extern __shared__ unsigned short smu[];
    unsigned short* xh = smu;                    // [128][PITCH] bf16
    unsigned short* xl = xh + 128 * PITCH;
    unsigned short* wh = xl + 128 * PITCH;
    unsigned short* wl = wh + 128 * PITCH;

    const int t    = threadIdx.x;
    const int row0 = blockIdx.x * MT;
    const int c0   = blockIdx.y * 128;

    // ---- stage x tile (embedding gather) + split: 2 threads/row, 64 floats each
    {
        int r  = t >> 1;
        int k0 = (t & 1) * 64;
        int idx = __ldg(seq + row0 + r);
        const float4* src = (const float4*)(emb + (size_t)idx * EMB + k0);
        #pragma unroll
        for (int i = 0; i < 16; i++) {
            float4 v = src[i];
            unsigned h0,l0,h1,l1,h2,l2,h3,l3;
            bsplit(v.x,h0,l0); bsplit(v.y,h1,l1);
            bsplit(v.z,h2,l2); bsplit(v.w,h3,l3);
            int o = r * PITCH + k0 + 4 * i;
            *(uint2*)(xh + o) = make_uint2(h0 | (h1 << 16), h2 | (h3 << 16));
            *(uint2*)(xl + o) = make_uint2(l0 | (l1 << 16), l2 | (l3 << 16));
        }
    }
    // ---- stage W tile + split
    {
        int c  = t >> 1;
        int k0 = (t & 1) * 64;
        const float4* src = (const float4*)(Wih + (size_t)(c0 + c) * EMB + k0);
        #pragma unroll
        for (int i = 0; i < 16; i++) {
            float4 v = src[i];
            unsigned h0,l0,h1,l1,h2,l2,h3,l3;
            bsplit(v.x,h0,l0); bsplit(v.y,h1,l1);
            bsplit(v.z,h2,l2); bsplit(v.w,h3,l3);
            int o = c * PITCH + k0 + 4 * i;
            *(uint2*)(wh + o) = make_uint2(h0 | (h1 << 16), h2 | (h3 << 16));
            *(uint2*)(wl + o) = make_uint2(l0 | (l1 << 16), l2 | (l3 << 16));
        }
    }
    __syncthreads();

    // ---- warp tiling: 4x2 warps; warp tile M=32 (2 m-subtiles), N=64 (8 n-subtiles)
    const int w     = t >> 5;
    const int lane  = t & 31;
    const int mrow0 = (w & 3) * 32;
    const int ncol0 = (w >> 2) * 64;
    const int g     = lane >> 2;       // 0..7
    const int tg    = lane & 3;        // 0..3

    float acc[2][8][4];
    #pragma unroll
    for (int m = 0; m < 2; m++)
        #pragma unroll
        for (int n = 0; n < 8; n++)
            #pragma unroll
            for (int i = 0; i < 4; i++) acc[m][n][i] = 0.f;

    #pragma unroll
    for (int kt = 0; kt < 8; kt++) {
        const int k0 = kt * 16;
        unsigned ah[2][4], al[2][4];
        #pragma unroll
        for (int m = 0; m < 2; m++) {
            const unsigned short* p = xh + (mrow0 + 16 * m + g) * PITCH + k0 + 2 * tg;
            const unsigned short* q = xl + (mrow0 + 16 * m + g) * PITCH + k0 + 2 * tg;
            ah[m][0] = *(const unsigned*)(p);
            ah[m][1] = *(const unsigned*)(p + 8 * PITCH);
            ah[m][2] = *(const unsigned*)(p + 8);
            ah[m][3] = *(const unsigned*)(p + 8 * PITCH + 8);
            al[m][0] = *(const unsigned*)(q);
            al[m][1] = *(const unsigned*)(q + 8 * PITCH);
            al[m][2] = *(const unsigned*)(q + 8);
            al[m][3] = *(const unsigned*)(q + 8 * PITCH + 8);
        }
        #pragma unroll
        for (int n = 0; n < 8; n++) {
            const unsigned short* p = wh + (ncol0 + 8 * n + g) * PITCH + k0 + 2 * tg;
            const unsigned short* q = wl + (ncol0 + 8 * n + g) * PITCH + k0 + 2 * tg;
            unsigned bh0 = *(const unsigned*)(p);
            unsigned bh1 = *(const unsigned*)(p + 8);
            unsigned bl0 = *(const unsigned*)(q);
            unsigned bl1 = *(const unsigned*)(q + 8);
            #pragma unroll
            for (int m = 0; m < 2; m++) {
                mma_bf16(acc[m][n], ah[m][0], ah[m][1], ah[m][2], ah[m][3], bh0, bh1);
                mma_bf16(acc[m][n], ah[m][0], ah[m][1], ah[m][2], ah[m][3], bl0, bl1);
                mma_bf16(acc[m][n], al[m][0], al[m][1], al[m][2], al[m][3], bh0, bh1);
            }
        }
    }

    // ---- epilogue: + bias, float2 stores to g_gx
    #pragma unroll
    for (int n = 0; n < 8; n++) {
        int col = c0 + ncol0 + n * 8 + 2 * tg;
        float2 bv = *(const float2*)(bih + col);
        #pragma unroll
        for (int m = 0; m < 2; m++) {
            int r0 = row0 + mrow0 + m * 16 + g;
            float2 v0 = { acc[m][n][0] + bv.x, acc[m][n][1] + bv.y };
            float2 v1 = { acc[m][n][2] + bv.x, acc[m][n][3] + bv.y };
            *(float2*)(g_gx + (size_t)r0 * G3 + col)       = v0;
            *(float2*)(g_gx + (size_t)(r0 + 8) * G3 + col) = v1;
        }
    }
}

// ---------------------------------------------------------------------------
// Kernel 2: GRU recurrence on tensor cores (R12 version verbatim — 427.9 us).
// 2-pass mma: lo-split packed into A rows 8-15 (formerly zero padding):
//   pass1 (B=w_hi): rows0-7 += hi*whi, rows8-15 += lo*whi
//   pass2 (B=w_lo): rows0-7 += hi*wlo, rows8-15 += lo*wlo
//   gh[g] = C[g] + C[g+8]   (exact (hi+lo)*(whi+wlo))
// ---------------------------------------------------------------------------
#define BM     8
#define GHPAD  388
#define HPITCH 68
#define SM2_BYTES ((49152 + BM * GHPAD + 2 * BM * HPITCH) * 4)

__device__ __forceinline__ float fsigmoid(float x) {
    return __fdividef(1.f, 1.f + __expf(-x));
}

__global__ __launch_bounds__(256) void gru_kernel(
    const float* __restrict__ Whh,
    const float* __restrict__ bhh,
    float*       __restrict__ out)
{
    extern __shared__ float sm[];
    uint2*    wfrag = (uint2*)sm;                      // [8w][6i][8j][2s][32l]
    float*    ghs   = sm + 49152;                      // [BM][GHPAD]
    unsigned* hhi   = (unsigned*)(ghs + BM * GHPAD);   // [BM][HPITCH] bf16x2
    unsigned* hlo   = hhi + BM * HPITCH;

    const int t  = threadIdx.x;
    const int w  = t >> 5;
    const int l  = t & 31;
    const int g  = l >> 2;
    const int tg = l & 3;
    const int b0 = blockIdx.x * BM;

    #pragma unroll
    for (int i = 0; i < 6; i++) {
        #pragma unroll
        for (int j = 0; j < 8; j++) {
            int n  = 48 * w + 8 * i + g;
            int kb = 16 * j + 2 * tg;
            const float* Wr = Whh + (size_t)n * HID;
            float w00 = Wr[kb],     w01 = Wr[kb + 1];
            float w08 = Wr[kb + 8], w09 = Wr[kb + 9];
            unsigned h00, l00, h01, l01, h08, l08, h09, l09;
            bsplit(w00, h00, l00);  bsplit(w01, h01, l01);
            bsplit(w08, h08, l08);  bsplit(w09, h09, l09);
            int base = ((w * 6 + i) * 8 + j) * 2;
            wfrag[(base + 0) * 32 + l] = make_uint2(h00 | (h01 << 16), h08 | (h09 << 16));
            wfrag[(base + 1) * 32 + l] = make_uint2(l00 | (l01 << 16), l08 | (l09 << 16));
        }
    }
    for (int p = t; p < 2 * BM * HPITCH; p += 256) hhi[p] = 0u;

    float2 bias[6];
    #pragma unroll
    for (int i = 0; i < 6; i++)
        bias[i] = *(const float2*)(bhh + 48 * w + 8 * i + 2 * tg);

    const int k2 = t & 63;
    const int rb = t >> 6;
    float h0a = 0.f, h0b = 0.f;
    float h1a = 0.f, h1b = 0.f;
    const size_t gx0 = ((size_t)(b0 + rb)     * T_SEQ) * G3 + 2 * k2;
    const size_t gx1 = ((size_t)(b0 + rb + 4) * T_SEQ) * G3 + 2 * k2;

    const uint2* pw = wfrag + (w * 96) * 32 + l;
    __syncthreads();

    for (int ts = 0; ts < T_SEQ; ts++) {
        const float* gp0 = g_gx + gx0 + (size_t)ts * G3;
        const float* gp1 = g_gx + gx1 + (size_t)ts * G3;
        float2 xr0 = __ldg((const float2*)(gp0));
        float2 xz0 = __ldg((const float2*)(gp0 + 128));
        float2 xn0 = __ldg((const float2*)(gp0 + 256));
        float2 xr1 = __ldg((const float2*)(gp1));
        float2 xz1 = __ldg((const float2*)(gp1 + 128));
        float2 xn1 = __ldg((const float2*)(gp1 + 256));

        float acc[6][4];
        #pragma unroll
        for (int i = 0; i < 6; i++)
            { acc[i][0]=0.f; acc[i][1]=0.f; acc[i][2]=0.f; acc[i][3]=0.f; }

        #pragma unroll
        for (int j = 0; j < 8; j++) {
            unsigned ahi0 = hhi[g * HPITCH + 8 * j + tg];
            unsigned ahi2 = hhi[g * HPITCH + 8 * j + tg + 4];
            unsigned alo0 = hlo[g * HPITCH + 8 * j + tg];
            unsigned alo2 = hlo[g * HPITCH + 8 * j + tg + 4];
            #pragma unroll
            for (int i = 0; i < 6; i++) {
                uint2 bh = pw[((i * 8 + j) * 2 + 0) * 32];
                uint2 bl = pw[((i * 8 + j) * 2 + 1) * 32];
                mma_bf16(acc[i], ahi0, alo0, ahi2, alo2, bh.x, bh.y);  // hi|lo vs w_hi
                mma_bf16(acc[i], ahi0, alo0, ahi2, alo2, bl.x, bl.y);  // hi|lo vs w_lo
            }
        }
        #pragma unroll
        for (int i = 0; i < 6; i++) {
            float2 v = { acc[i][0] + acc[i][2] + bias[i].x,
                         acc[i][1] + acc[i][3] + bias[i].y };
            *(float2*)(ghs + g * GHPAD + 48 * w + 8 * i + 2 * tg) = v;
        }
        __syncthreads();

        {
            float2 hr = *(const float2*)(ghs + rb * GHPAD + 2 * k2);
            float2 hz = *(const float2*)(ghs + rb * GHPAD + 128 + 2 * k2);
            float2 hn = *(const float2*)(ghs + rb * GHPAD + 256 + 2 * k2);
            float r_a = fsigmoid(xr0.x + hr.x), r_b = fsigmoid(xr0.y + hr.y);
            float z_a = fsigmoid(xz0.x + hz.x), z_b = fsigmoid(xz0.y + hz.y);
            float n_a = 2.f * fsigmoid(2.f * (xn0.x + r_a * hn.x)) - 1.f;
            float n_b = 2.f * fsigmoid(2.f * (xn0.y + r_b * hn.y)) - 1.f;
            h0a = (1.f - z_a) * n_a + z_a * h0a;
            h0b = (1.f - z_b) * n_b + z_b * h0b;
        }
        {
            float2 hr = *(const float2*)(ghs + (rb + 4) * GHPAD + 2 * k2);
            float2 hz = *(const float2*)(ghs + (rb + 4) * GHPAD + 128 + 2 * k2);
            float2 hn = *(const float2*)(ghs + (rb + 4) * GHPAD + 256 + 2 * k2);
            float r_a = fsigmoid(xr1.x + hr.x), r_b = fsigmoid(xr1.y + hr.y);
            float z_a = fsigmoid(xz1.x + hz.x), z_b = fsigmoid(xz1.y + hz.y);
            float n_a = 2.f * fsigmoid(2.f * (xn1.x + r_a * hn.x)) - 1.f;
            float n_b = 2.f * fsigmoid(2.f * (xn1.y + r_b * hn.y)) - 1.f;
            h1a = (1.f - z_a) * n_a + z_a * h1a;
            h1b = (1.f - z_b) * n_b + z_b * h1b;
        }
        {
            unsigned ha, la, hb, lb;
            bsplit(h0a, ha, la);  bsplit(h0b, hb, lb);
            hhi[rb * HPITCH + k2] = ha | (hb << 16);
            hlo[rb * HPITCH + k2] = la | (lb << 16);
            bsplit(h1a, ha, la);  bsplit(h1b, hb, lb);
            hhi[(rb + 4) * HPITCH + k2] = ha | (hb << 16);
            hlo[(rb + 4) * HPITCH + k2] = la | (lb << 16);
        }
        __syncthreads();
    }

    {
        float2 v0 = { h0a, h0b };
        float2 v1 = { h1a, h1b };
        *(float2*)(out + (size_t)(b0 + rb)     * HID + 2 * k2) = v0;
        *(float2*)(out + (size_t)(b0 + rb + 4) * HID + 2 * k2) = v1;
    }
}

// ---------------------------------------------------------------------------
// Launch
// ---------------------------------------------------------------------------
extern "C" void kernel_launch(void* const* d_in, const int* in_sizes, int n_in,
                              void* d_out, int out_size)
{
    const int*   seq = (const int*)  d_in[0];  // [1024, 200] int32
    const float* emb = (const float*)d_in[1];  // [100000, 128]
    const float* Wih = (const float*)d_in[2];  // [384, 128]
    const float* Whh = (const float*)d_in[3];  // [384, 128]
    const float* bih = (const float*)d_in[4];  // [384]
    const float* bhh = (const float*)d_in[5];  // [384]
    float* out = (float*)d_out;                // [1024, 128]

    cudaFuncSetAttribute(gx_kernel,  cudaFuncAttributeMaxDynamicSharedMemorySize, SM1_BYTES);
    cudaFuncSetAttribute(gru_kernel, cudaFuncAttributeMaxDynamicSharedMemorySize, SM2_BYTES);

    dim3 grid1(NROWS / MT, G3 / 128);          // 1600 x 3
    gx_kernel<<<grid1, 256, SM1_BYTES>>>(seq, emb, Wih, bih);

    gru_kernel<<<BATCH / BM, 256, SM2_BYTES>>>(Whh, bhh, out);
}

// round 16
// speedup vs baseline: 1.1962x; 1.0322x over previous
#include <cuda_runtime.h>
#include <cstdint>

// Problem constants
#define T_SEQ 200
#define BATCH 1024
#define EMB   128
#define HID   128
#define G3    384          // 3*HID, gate order r,z,n
#define NROWS (BATCH * T_SEQ)

// 314 MB scratch for gx = x @ W_ih^T + b_ih  (static __device__: allocation-free)
__device__ float g_gx[(size_t)NROWS * G3];

// ---- bf16 split helpers (RNE via bit trick, matches cvt.rn.bf16) ----
__device__ __forceinline__ unsigned bf16bits(float x) {      // top-16 bits, rounded
    unsigned u = __float_as_uint(x);
    return ((u + 0x7fffu + ((u >> 16) & 1u)) & 0xffff0000u);
}
__device__ __forceinline__ void bsplit(float x, unsigned& h16, unsigned& l16) {
    unsigned uh = bf16bits(x);
    float hi = __uint_as_float(uh);
    float lo = x - hi;
    h16 = uh >> 16;
    l16 = bf16bits(lo) >> 16;
}

// D += A*B  (m16n8k16 bf16, fp32 accum)
__device__ __forceinline__ void mma_bf16(float* c,
                                         unsigned a0, unsigned a1, unsigned a2, unsigned a3,
                                         unsigned b0, unsigned b1) {
    asm("mma.sync.aligned.m16n8k16.row.col.f32.bf16.bf16.f32 "
        "{%0,%1,%2,%3}, {%4,%5,%6,%7}, {%8,%9}, {%0,%1,%2,%3};"
        : "+f"(c[0]), "+f"(c[1]), "+f"(c[2]), "+f"(c[3])
        : "r"(a0), "r"(a1), "r"(a2), "r"(a3), "r"(b0), "r"(b1));
}

// ---------------------------------------------------------------------------
// Kernel 1: fused embedding gather + input GEMM on tensor cores (bf16 3-pass).
// R8 design; grid dims SWAPPED so the 3 col-blocks of a row-block are adjacent
// in schedule -> x gather rows + W tiles stay L2-hot (saves ~200 MB DRAM).
// ---------------------------------------------------------------------------
#define MT    128
#define PITCH 136
#define SM1_BYTES (4 * 128 * PITCH * 2)

__global__ __launch_bounds__(256) void gx_kernel(
    const int*   __restrict__ seq,
    const float* __restrict__ emb,
    const float* __restrict__ Wih,
    const float* __restrict__ bih)
{
    extern __shared__ unsigned short smu[];
    unsigned short* xh = smu;                    // [128][PITCH] bf16
    unsigned short* xl = xh + 128 * PITCH;
    unsigned short* wh = xl + 128 * PITCH;
    unsigned short* wl = wh + 128 * PITCH;

    const int t    = threadIdx.x;
    const int row0 = blockIdx.y * MT;            // swapped
    const int c0   = blockIdx.x * 128;           // swapped (fastest-varying)

    // ---- stage x tile (embedding gather) + split: 2 threads/row, 64 floats each
    {
        int r  = t >> 1;
        int k0 = (t & 1) * 64;
        int idx = __ldg(seq + row0 + r);
        const float4* src = (const float4*)(emb + (size_t)idx * EMB + k0);
        #pragma unroll
        for (int i = 0; i < 16; i++) {
            float4 v = src[i];
            unsigned h0,l0,h1,l1,h2,l2,h3,l3;
            bsplit(v.x,h0,l0); bsplit(v.y,h1,l1);
            bsplit(v.z,h2,l2); bsplit(v.w,h3,l3);
            int o = r * PITCH + k0 + 4 * i;
            *(uint2*)(xh + o) = make_uint2(h0 | (h1 << 16), h2 | (h3 << 16));
            *(uint2*)(xl + o) = make_uint2(l0 | (l1 << 16), l2 | (l3 << 16));
        }
    }
    // ---- stage W tile + split
    {
        int c  = t >> 1;
        int k0 = (t & 1) * 64;
        const float4* src = (const float4*)(Wih + (size_t)(c0 + c) * EMB + k0);
        #pragma unroll
        for (int i = 0; i < 16; i++) {
            float4 v = src[i];
            unsigned h0,l0,h1,l1,h2,l2,h3,l3;
            bsplit(v.x,h0,l0); bsplit(v.y,h1,l1);
            bsplit(v.z,h2,l2); bsplit(v.w,h3,l3);
            int o = c * PITCH + k0 + 4 * i;
            *(uint2*)(wh + o) = make_uint2(h0 | (h1 << 16), h2 | (h3 << 16));
            *(uint2*)(wl + o) = make_uint2(l0 | (l1 << 16), l2 | (l3 << 16));
        }
    }
    __syncthreads();

    // ---- warp tiling: 4x2 warps; warp tile M=32 (2 m-subtiles), N=64 (8 n-subtiles)
    const int w     = t >> 5;
    const int lane  = t & 31;
    const int mrow0 = (w & 3) * 32;
    const int ncol0 = (w >> 2) * 64;
    const int g     = lane >> 2;       // 0..7
    const int tg    = lane & 3;        // 0..3

    float acc[2][8][4];
    #pragma unroll
    for (int m = 0; m < 2; m++)
        #pragma unroll
        for (int n = 0; n < 8; n++)
            #pragma unroll
            for (int i = 0; i < 4; i++) acc[m][n][i] = 0.f;

    #pragma unroll
    for (int kt = 0; kt < 8; kt++) {
        const int k0 = kt * 16;
        unsigned ah[2][4], al[2][4];
        #pragma unroll
        for (int m = 0; m < 2; m++) {
            const unsigned short* p = xh + (mrow0 + 16 * m + g) * PITCH + k0 + 2 * tg;
            const unsigned short* q = xl + (mrow0 + 16 * m + g) * PITCH + k0 + 2 * tg;
            ah[m][0] = *(const unsigned*)(p);
            ah[m][1] = *(const unsigned*)(p + 8 * PITCH);
            ah[m][2] = *(const unsigned*)(p + 8);
            ah[m][3] = *(const unsigned*)(p + 8 * PITCH + 8);
            al[m][0] = *(const unsigned*)(q);
            al[m][1] = *(const unsigned*)(q + 8 * PITCH);
            al[m][2] = *(const unsigned*)(q + 8);
            al[m][3] = *(const unsigned*)(q + 8 * PITCH + 8);
        }
        #pragma unroll
        for (int n = 0; n < 8; n++) {
            const unsigned short* p = wh + (ncol0 + 8 * n + g) * PITCH + k0 + 2 * tg;
            const unsigned short* q = wl + (ncol0 + 8 * n + g) * PITCH + k0 + 2 * tg;
            unsigned bh0 = *(const unsigned*)(p);
            unsigned bh1 = *(const unsigned*)(p + 8);
            unsigned bl0 = *(const unsigned*)(q);
            unsigned bl1 = *(const unsigned*)(q + 8);
            #pragma unroll
            for (int m = 0; m < 2; m++) {
                mma_bf16(acc[m][n], ah[m][0], ah[m][1], ah[m][2], ah[m][3], bh0, bh1);
                mma_bf16(acc[m][n], ah[m][0], ah[m][1], ah[m][2], ah[m][3], bl0, bl1);
                mma_bf16(acc[m][n], al[m][0], al[m][1], al[m][2], al[m][3], bh0, bh1);
            }
        }
    }

    // ---- epilogue: + bias, float2 stores to g_gx
    #pragma unroll
    for (int n = 0; n < 8; n++) {
        int col = c0 + ncol0 + n * 8 + 2 * tg;
        float2 bv = *(const float2*)(bih + col);
        #pragma unroll
        for (int m = 0; m < 2; m++) {
            int r0 = row0 + mrow0 + m * 16 + g;
            float2 v0 = { acc[m][n][0] + bv.x, acc[m][n][1] + bv.y };
            float2 v1 = { acc[m][n][2] + bv.x, acc[m][n][3] + bv.y };
            *(float2*)(g_gx + (size_t)r0 * G3 + col)       = v0;
            *(float2*)(g_gx + (size_t)(r0 + 8) * G3 + col) = v1;
        }
    }
}

// ---------------------------------------------------------------------------
// Kernel 2: GRU recurrence on tensor cores, 16 WARPS (512 threads).
// Warp w owns 24 gates (3 n-tiles: n = 24w + 8i + g, i<3). Per-SMSP HMMA work
// unchanged (4 warps x 48), but 4 warps/SMSP hide the ghs/gate/bsplit latency
// chain that was exposed at 2 warps/SMSP (issue was 25.6%).
// 2-pass mma: lo-split packed into A rows 8-15; gh = c0+c2 (exact).
// ---------------------------------------------------------------------------
#define BM     8
#define NT2    512
#define GHPAD  388
#define HPITCH 68
#define SM2_BYTES ((49152 + BM * GHPAD + 2 * BM * HPITCH) * 4)

__device__ __forceinline__ float fsigmoid(float x) {
    return __fdividef(1.f, 1.f + __expf(-x));
}

__global__ __launch_bounds__(NT2) void gru_kernel(
    const float* __restrict__ Whh,
    const float* __restrict__ bhh,
    float*       __restrict__ out)
{
    extern __shared__ float sm[];
    uint2*    wfrag = (uint2*)sm;                      // [16w][3i][8j][2s][32l]
    float*    ghs   = sm + 49152;                      // [BM][GHPAD]
    unsigned* hhi   = (unsigned*)(ghs + BM * GHPAD);   // [BM][HPITCH] bf16x2
    unsigned* hlo   = hhi + BM * HPITCH;

    const int t  = threadIdx.x;
    const int w  = t >> 5;        // 0..15
    const int l  = t & 31;
    const int g  = l >> 2;
    const int tg = l & 3;
    const int b0 = blockIdx.x * BM;

    // ---- precompute W_hh fragments (warp w: gates 24w .. 24w+23)
    #pragma unroll
    for (int i = 0; i < 3; i++) {
        #pragma unroll
        for (int j = 0; j < 8; j++) {
            int n  = 24 * w + 8 * i + g;
            int kb = 16 * j + 2 * tg;
            const float* Wr = Whh + (size_t)n * HID;
            float w00 = Wr[kb],     w01 = Wr[kb + 1];
            float w08 = Wr[kb + 8], w09 = Wr[kb + 9];
            unsigned h00, l00, h01, l01, h08, l08, h09, l09;
            bsplit(w00, h00, l00);  bsplit(w01, h01, l01);
            bsplit(w08, h08, l08);  bsplit(w09, h09, l09);
            int base = ((w * 3 + i) * 8 + j) * 2;
            wfrag[(base + 0) * 32 + l] = make_uint2(h00 | (h01 << 16), h08 | (h09 << 16));
            wfrag[(base + 1) * 32 + l] = make_uint2(l00 | (l01 << 16), l08 | (l09 << 16));
        }
    }
    for (int p = t; p < 2 * BM * HPITCH; p += NT2) hhi[p] = 0u;

    float2 bias[3];
    #pragma unroll
    for (int i = 0; i < 3; i++)
        bias[i] = *(const float2*)(bhh + 24 * w + 8 * i + 2 * tg);

    // phase-2 mapping: thread -> (row rb, cols 2k2, 2k2+1); 512 threads = 1024 pos
    const int k2 = t & 63;
    const int rb = t >> 6;        // 0..7
    float h0a = 0.f, h0b = 0.f;
    const size_t gx0 = ((size_t)(b0 + rb) * T_SEQ) * G3 + 2 * k2;

    const uint2* pw = wfrag + (w * 48) * 32 + l;
    __syncthreads();

    for (int ts = 0; ts < T_SEQ; ts++) {
        const float* gp0 = g_gx + gx0 + (size_t)ts * G3;
        float2 xr0 = __ldg((const float2*)(gp0));
        float2 xz0 = __ldg((const float2*)(gp0 + 128));
        float2 xn0 = __ldg((const float2*)(gp0 + 256));

        float acc[3][4];
        #pragma unroll
        for (int i = 0; i < 3; i++)
            { acc[i][0]=0.f; acc[i][1]=0.f; acc[i][2]=0.f; acc[i][3]=0.f; }

        #pragma unroll
        for (int j = 0; j < 8; j++) {
            unsigned ahi0 = hhi[g * HPITCH + 8 * j + tg];
            unsigned ahi2 = hhi[g * HPITCH + 8 * j + tg + 4];
            unsigned alo0 = hlo[g * HPITCH + 8 * j + tg];
            unsigned alo2 = hlo[g * HPITCH + 8 * j + tg + 4];
            #pragma unroll
            for (int i = 0; i < 3; i++) {
                uint2 bh = pw[((i * 8 + j) * 2 + 0) * 32];
                uint2 bl = pw[((i * 8 + j) * 2 + 1) * 32];
                mma_bf16(acc[i], ahi0, alo0, ahi2, alo2, bh.x, bh.y);  // hi|lo vs w_hi
                mma_bf16(acc[i], ahi0, alo0, ahi2, alo2, bl.x, bl.y);  // hi|lo vs w_lo
            }
        }
        #pragma unroll
        for (int i = 0; i < 3; i++) {
            float2 v = { acc[i][0] + acc[i][2] + bias[i].x,
                         acc[i][1] + acc[i][3] + bias[i].y };
            *(float2*)(ghs + g * GHPAD + 24 * w + 8 * i + 2 * tg) = v;
        }
        __syncthreads();

        {
            float2 hr = *(const float2*)(ghs + rb * GHPAD + 2 * k2);
            float2 hz = *(const float2*)(ghs + rb * GHPAD + 128 + 2 * k2);
            float2 hn = *(const float2*)(ghs + rb * GHPAD + 256 + 2 * k2);
            float r_a = fsigmoid(xr0.x + hr.x), r_b = fsigmoid(xr0.y + hr.y);
            float z_a = fsigmoid(xz0.x + hz.x), z_b = fsigmoid(xz0.y + hz.y);
            float n_a = 2.f * fsigmoid(2.f * (xn0.x + r_a * hn.x)) - 1.f;
            float n_b = 2.f * fsigmoid(2.f * (xn0.y + r_b * hn.y)) - 1.f;
            h0a = (1.f - z_a) * n_a + z_a * h0a;
            h0b = (1.f - z_b) * n_b + z_b * h0b;
        }
        {
            unsigned ha, la, hb, lb;
            bsplit(h0a, ha, la);  bsplit(h0b, hb, lb);
            hhi[rb * HPITCH + k2] = ha | (hb << 16);
            hlo[rb * HPITCH + k2] = la | (lb << 16);
        }
        __syncthreads();
    }

    {
        float2 v0 = { h0a, h0b };
        *(float2*)(out + (size_t)(b0 + rb) * HID + 2 * k2) = v0;
    }
}

// ---------------------------------------------------------------------------
// Launch
// ---------------------------------------------------------------------------
extern "C" void kernel_launch(void* const* d_in, const int* in_sizes, int n_in,
                              void* d_out, int out_size)
{
    const int*   seq = (const int*)  d_in[0];  // [1024, 200] int32
    const float* emb = (const float*)d_in[1];  // [100000, 128]
    const float* Wih = (const float*)d_in[2];  // [384, 128]
    const float* Whh = (const float*)d_in[3];  // [384, 128]
    const float* bih = (const float*)d_in[4];  // [384]
    const float* bhh = (const float*)d_in[5];  // [384]
    float* out = (float*)d_out;                // [1024, 128]

    cudaFuncSetAttribute(gx_kernel,  cudaFuncAttributeMaxDynamicSharedMemorySize, SM1_BYTES);
    cudaFuncSetAttribute(gru_kernel, cudaFuncAttributeMaxDynamicSharedMemorySize, SM2_BYTES);

    dim3 grid1(G3 / 128, NROWS / MT);          // 3 x 1600 (col-blocks fastest)
    gx_kernel<<<grid1, 256, SM1_BYTES>>>(seq, emb, Wih, bih);

    gru_kernel<<<BATCH / BM, NT2, SM2_BYTES>>>(Whh, bhh, out);
}

// round 17
// speedup vs baseline: 1.2417x; 1.0380x over previous
#include <cuda_runtime.h>
#include <cstdint>

// Problem constants
#define T_SEQ 200
#define BATCH 1024
#define EMB   128
#define HID   128
#define G3    384          // 3*HID, gate order r,z,n
#define NROWS (BATCH * T_SEQ)

// 314 MB scratch for gx = x @ W_ih^T + b_ih  (static __device__: allocation-free)
__device__ float g_gx[(size_t)NROWS * G3];

// ---- bf16 split helpers (RNE via bit trick, matches cvt.rn.bf16) ----
__device__ __forceinline__ unsigned bf16bits(float x) {      // top-16 bits, rounded
    unsigned u = __float_as_uint(x);
    return ((u + 0x7fffu + ((u >> 16) & 1u)) & 0xffff0000u);
}
__device__ __forceinline__ void bsplit(float x, unsigned& h16, unsigned& l16) {
    unsigned uh = bf16bits(x);
    float hi = __uint_as_float(uh);
    float lo = x - hi;
    h16 = uh >> 16;
    l16 = bf16bits(lo) >> 16;
}

// D += A*B  (m16n8k16 bf16, fp32 accum)
__device__ __forceinline__ void mma_bf16(float* c,
                                         unsigned a0, unsigned a1, unsigned a2, unsigned a3,
                                         unsigned b0, unsigned b1) {
    asm("mma.sync.aligned.m16n8k16.row.col.f32.bf16.bf16.f32 "
        "{%0,%1,%2,%3}, {%4,%5,%6,%7}, {%8,%9}, {%0,%1,%2,%3};"
        : "+f"(c[0]), "+f"(c[1]), "+f"(c[2]), "+f"(c[3])
        : "r"(a0), "r"(a1), "r"(a2), "r"(a3), "r"(b0), "r"(b1));
}

// ---------------------------------------------------------------------------
// Kernel 1: fused embedding gather + input GEMM on tensor cores (bf16 3-pass).
// NEW: epilogue stages the 128x128 fp32 output tile in SMEM (reusing the
// operand buffers) then writes g_gx with 8-threads-per-row float4 stores:
// every warp STG = 4 x 128 B full transactions (was scattered 8 B float2s).
// ---------------------------------------------------------------------------
#define MT    128
#define PITCH 136
#define OPITCH 132
#define SM1_BYTES (4 * 128 * PITCH * 2)

__global__ __launch_bounds__(256) void gx_kernel(
    const int*   __restrict__ seq,
    const float* __restrict__ emb,
    const float* __restrict__ Wih,
    const float* __restrict__ bih)
{
    extern __shared__ unsigned short smu[];
    unsigned short* xh = smu;                    // [128][PITCH] bf16
    unsigned short* xl = xh + 128 * PITCH;
    unsigned short* wh = xl + 128 * PITCH;
    unsigned short* wl = wh + 128 * PITCH;

    const int t    = threadIdx.x;
    const int row0 = blockIdx.y * MT;
    const int c0   = blockIdx.x * 128;           // col-blocks fastest-varying

    // ---- stage x tile (embedding gather) + split: 2 threads/row, 64 floats each
    {
        int r  = t >> 1;
        int k0 = (t & 1) * 64;
        int idx = __ldg(seq + row0 + r);
        const float4* src = (const float4*)(emb + (size_t)idx * EMB + k0);
        #pragma unroll
        for (int i = 0; i < 16; i++) {
            float4 v = src[i];
            unsigned h0,l0,h1,l1,h2,l2,h3,l3;
            bsplit(v.x,h0,l0); bsplit(v.y,h1,l1);
            bsplit(v.z,h2,l2); bsplit(v.w,h3,l3);
            int o = r * PITCH + k0 + 4 * i;
            *(uint2*)(xh + o) = make_uint2(h0 | (h1 << 16), h2 | (h3 << 16));
            *(uint2*)(xl + o) = make_uint2(l0 | (l1 << 16), l2 | (l3 << 16));
        }
    }
    // ---- stage W tile + split
    {
        int c  = t >> 1;
        int k0 = (t & 1) * 64;
        const float4* src = (const float4*)(Wih + (size_t)(c0 + c) * EMB + k0);
        #pragma unroll
        for (int i = 0; i < 16; i++) {
            float4 v = src[i];
            unsigned h0,l0,h1,l1,h2,l2,h3,l3;
            bsplit(v.x,h0,l0); bsplit(v.y,h1,l1);
            bsplit(v.z,h2,l2); bsplit(v.w,h3,l3);
            int o = c * PITCH + k0 + 4 * i;
            *(uint2*)(wh + o) = make_uint2(h0 | (h1 << 16), h2 | (h3 << 16));
            *(uint2*)(wl + o) = make_uint2(l0 | (l1 << 16), l2 | (l3 << 16));
        }
    }
    __syncthreads();

    // ---- warp tiling: 4x2 warps; warp tile M=32 (2 m-subtiles), N=64 (8 n-subtiles)
    const int w     = t >> 5;
    const int lane  = t & 31;
    const int mrow0 = (w & 3) * 32;
    const int ncol0 = (w >> 2) * 64;
    const int g     = lane >> 2;       // 0..7
    const int tg    = lane & 3;        // 0..3

    float acc[2][8][4];
    #pragma unroll
    for (int m = 0; m < 2; m++)
        #pragma unroll
        for (int n = 0; n < 8; n++)
            #pragma unroll
            for (int i = 0; i < 4; i++) acc[m][n][i] = 0.f;

    #pragma unroll
    for (int kt = 0; kt < 8; kt++) {
        const int k0 = kt * 16;
        unsigned ah[2][4], al[2][4];
        #pragma unroll
        for (int m = 0; m < 2; m++) {
            const unsigned short* p = xh + (mrow0 + 16 * m + g) * PITCH + k0 + 2 * tg;
            const unsigned short* q = xl + (mrow0 + 16 * m + g) * PITCH + k0 + 2 * tg;
            ah[m][0] = *(const unsigned*)(p);
            ah[m][1] = *(const unsigned*)(p + 8 * PITCH);
            ah[m][2] = *(const unsigned*)(p + 8);
            ah[m][3] = *(const unsigned*)(p + 8 * PITCH + 8);
            al[m][0] = *(const unsigned*)(q);
            al[m][1] = *(const unsigned*)(q + 8 * PITCH);
            al[m][2] = *(const unsigned*)(q + 8);
            al[m][3] = *(const unsigned*)(q + 8 * PITCH + 8);
        }
        #pragma unroll
        for (int n = 0; n < 8; n++) {
            const unsigned short* p = wh + (ncol0 + 8 * n + g) * PITCH + k0 + 2 * tg;
            const unsigned short* q = wl + (ncol0 + 8 * n + g) * PITCH + k0 + 2 * tg;
            unsigned bh0 = *(const unsigned*)(p);
            unsigned bh1 = *(const unsigned*)(p + 8);
            unsigned bl0 = *(const unsigned*)(q);
            unsigned bl1 = *(const unsigned*)(q + 8);
            #pragma unroll
            for (int m = 0; m < 2; m++) {
                mma_bf16(acc[m][n], ah[m][0], ah[m][1], ah[m][2], ah[m][3], bh0, bh1);
                mma_bf16(acc[m][n], ah[m][0], ah[m][1], ah[m][2], ah[m][3], bl0, bl1);
                mma_bf16(acc[m][n], al[m][0], al[m][1], al[m][2], al[m][3], bh0, bh1);
            }
        }
    }
    __syncthreads();   // tile reads done; reuse SMEM as output staging

    // ---- epilogue stage 1: acc (+bias) -> SMEM output tile [128][OPITCH]
    float* os = (float*)smu;
    #pragma unroll
    for (int n = 0; n < 8; n++) {
        int col = ncol0 + n * 8 + 2 * tg;
        float2 bv = *(const float2*)(bih + c0 + col);
        #pragma unroll
        for (int m = 0; m < 2; m++) {
            int r0 = mrow0 + 16 * m + g;
            float2 v0 = { acc[m][n][0] + bv.x, acc[m][n][1] + bv.y };
            float2 v1 = { acc[m][n][2] + bv.x, acc[m][n][3] + bv.y };
            *(float2*)(os + r0 * OPITCH + col)       = v0;
            *(float2*)(os + (r0 + 8) * OPITCH + col) = v1;
        }
    }
    __syncthreads();

    // ---- epilogue stage 2: coalesced stores (8 threads/row, float4 each)
    {
        const int rr0 = t >> 3;            // 0..31
        const int kx  = (t & 7) * 4;       // 0..28
        #pragma unroll
        for (int i = 0; i < 4; i++) {
            int rr = rr0 + 32 * i;
            float* dst = g_gx + (size_t)(row0 + rr) * G3 + c0;
            const float* src = os + rr * OPITCH;
            #pragma unroll
            for (int p = 0; p < 4; p++)
                *(float4*)(dst + kx + 32 * p) = *(const float4*)(src + kx + 32 * p);
        }
    }
}

// ---------------------------------------------------------------------------
// Kernel 2: GRU recurrence on tensor cores, 16 warps (512 threads).
// NEW: w_hi fragments live in REGISTERS (48 regs/thread, computed in the
// precompute loop); only w_lo stays in SMEM -> per-step B-fragment smem
// traffic halves (196 -> ~98 KB/CTA-step), wfrag SMEM 196 -> 98 KB.
// 2-pass mma: lo-split packed into A rows 8-15; gh = c0+c2 (exact).
// ---------------------------------------------------------------------------
#define BM     8
#define NT2    512
#define GHPAD  388
#define HPITCH 68
#define WFRAG_LO_WORDS (16 * 3 * 8 * 32 * 2)   // uint per: 16w*3i*8j*32l uint2
#define SM2_BYTES ((WFRAG_LO_WORDS + BM * GHPAD + 2 * BM * HPITCH) * 4)

__device__ __forceinline__ float fsigmoid(float x) {
    return __fdividef(1.f, 1.f + __expf(-x));
}

__global__ __launch_bounds__(NT2) void gru_kernel(
    const float* __restrict__ Whh,
    const float* __restrict__ bhh,
    float*       __restrict__ out)
{
    extern __shared__ float sm[];
    uint2*    wflo = (uint2*)sm;                           // [16w][3i][8j][32l]
    float*    ghs  = sm + WFRAG_LO_WORDS;                  // [BM][GHPAD]
    unsigned* hhi  = (unsigned*)(ghs + BM * GHPAD);        // [BM][HPITCH] bf16x2
    unsigned* hlo  = hhi + BM * HPITCH;

    const int t  = threadIdx.x;
    const int w  = t >> 5;        // 0..15
    const int l  = t & 31;
    const int g  = l >> 2;
    const int tg = l & 3;
    const int b0 = blockIdx.x * BM;

    // ---- precompute W_hh fragments: hi -> registers, lo -> SMEM
    uint2 bwh[3][8];
    #pragma unroll
    for (int i = 0; i < 3; i++) {
        #pragma unroll
        for (int j = 0; j < 8; j++) {
            int n  = 24 * w + 8 * i + g;
            int kb = 16 * j + 2 * tg;
            const float* Wr = Whh + (size_t)n * HID;
            float w00 = Wr[kb],     w01 = Wr[kb + 1];
            float w08 = Wr[kb + 8], w09 = Wr[kb + 9];
            unsigned h00, l00, h01, l01, h08, l08, h09, l09;
            bsplit(w00, h00, l00);  bsplit(w01, h01, l01);
            bsplit(w08, h08, l08);  bsplit(w09, h09, l09);
            bwh[i][j] = make_uint2(h00 | (h01 << 16), h08 | (h09 << 16));
            wflo[((w * 3 + i) * 8 + j) * 32 + l] =
                make_uint2(l00 | (l01 << 16), l08 | (l09 << 16));
        }
    }
    for (int p = t; p < 2 * BM * HPITCH; p += NT2) hhi[p] = 0u;

    float2 bias[3];
    #pragma unroll
    for (int i = 0; i < 3; i++)
        bias[i] = *(const float2*)(bhh + 24 * w + 8 * i + 2 * tg);

    // phase-2 mapping: thread -> (row rb, cols 2k2, 2k2+1)
    const int k2 = t & 63;
    const int rb = t >> 6;        // 0..7
    float h0a = 0.f, h0b = 0.f;
    const size_t gx0 = ((size_t)(b0 + rb) * T_SEQ) * G3 + 2 * k2;

    const uint2* pwlo = wflo + (w * 24) * 32 + l;
    __syncthreads();

    for (int ts = 0; ts < T_SEQ; ts++) {
        const float* gp0 = g_gx + gx0 + (size_t)ts * G3;
        float2 xr0 = __ldg((const float2*)(gp0));
        float2 xz0 = __ldg((const float2*)(gp0 + 128));
        float2 xn0 = __ldg((const float2*)(gp0 + 256));

        float acc[3][4];
        #pragma unroll
        for (int i = 0; i < 3; i++)
            { acc[i][0]=0.f; acc[i][1]=0.f; acc[i][2]=0.f; acc[i][3]=0.f; }

        #pragma unroll
        for (int j = 0; j < 8; j++) {
            unsigned ahi0 = hhi[g * HPITCH + 8 * j + tg];
            unsigned ahi2 = hhi[g * HPITCH + 8 * j + tg + 4];
            unsigned alo0 = hlo[g * HPITCH + 8 * j + tg];
            unsigned alo2 = hlo[g * HPITCH + 8 * j + tg + 4];
            #pragma unroll
            for (int i = 0; i < 3; i++) {
                uint2 bl = pwlo[(i * 8 + j) * 32];
                mma_bf16(acc[i], ahi0, alo0, ahi2, alo2,
                         bwh[i][j].x, bwh[i][j].y);           // hi|lo vs w_hi (regs)
                mma_bf16(acc[i], ahi0, alo0, ahi2, alo2, bl.x, bl.y);  // vs w_lo
            }
        }
        #pragma unroll
        for (int i = 0; i < 3; i++) {
            float2 v = { acc[i][0] + acc[i][2] + bias[i].x,
                         acc[i][1] + acc[i][3] + bias[i].y };
            *(float2*)(ghs + g * GHPAD + 24 * w + 8 * i + 2 * tg) = v;
        }
        __syncthreads();

        {
            float2 hr = *(const float2*)(ghs + rb * GHPAD + 2 * k2);
            float2 hz = *(const float2*)(ghs + rb * GHPAD + 128 + 2 * k2);
            float2 hn = *(const float2*)(ghs + rb * GHPAD + 256 + 2 * k2);
            float r_a = fsigmoid(xr0.x + hr.x), r_b = fsigmoid(xr0.y + hr.y);
            float z_a = fsigmoid(xz0.x + hz.x), z_b = fsigmoid(xz0.y + hz.y);
            float n_a = 2.f * fsigmoid(2.f * (xn0.x + r_a * hn.x)) - 1.f;
            float n_b = 2.f * fsigmoid(2.f * (xn0.y + r_b * hn.y)) - 1.f;
            h0a = (1.f - z_a) * n_a + z_a * h0a;
            h0b = (1.f - z_b) * n_b + z_b * h0b;
        }
        {
            unsigned ha, la, hb, lb;
            bsplit(h0a, ha, la);  bsplit(h0b, hb, lb);
            hhi[rb * HPITCH + k2] = ha | (hb << 16);
            hlo[rb * HPITCH + k2] = la | (lb << 16);
        }
        __syncthreads();
    }

    {
        float2 v0 = { h0a, h0b };
        *(float2*)(out + (size_t)(b0 + rb) * HID + 2 * k2) = v0;
    }
}

// ---------------------------------------------------------------------------
// Launch
// ---------------------------------------------------------------------------
extern "C" void kernel_launch(void* const* d_in, const int* in_sizes, int n_in,
                              void* d_out, int out_size)
{
    const int*   seq = (const int*)  d_in[0];  // [1024, 200] int32
    const float* emb = (const float*)d_in[1];  // [100000, 128]
    const float* Wih = (const float*)d_in[2];  // [384, 128]
    const float* Whh = (const float*)d_in[3];  // [384, 128]
    const float* bih = (const float*)d_in[4];  // [384]
    const float* bhh = (const float*)d_in[5];  // [384]
    float* out = (float*)d_out;                // [1024, 128]

    cudaFuncSetAttribute(gx_kernel,  cudaFuncAttributeMaxDynamicSharedMemorySize, SM1_BYTES);
    cudaFuncSetAttribute(gru_kernel, cudaFuncAttributeMaxDynamicSharedMemorySize, SM2_BYTES);

    dim3 grid1(G3 / 128, NROWS / MT);          // 3 x 1600 (col-blocks fastest)
    gx_kernel<<<grid1, 256, SM1_BYTES>>>(seq, emb, Wih, bih);

    gru_kernel<<<BATCH / BM, NT2, SM2_BYTES>>>(Whh, bhh, out);
}